// round 11
// baseline (speedup 1.0000x reference)
#include <cuda_runtime.h>
#include <cuda_bf16.h>
#include <cstdint>
#include <math.h>

#define B_    2
#define T_    2048
#define C_    1024
#define H_    16
#define D_    64
#define M_    4096
#define QKVN  3072
#define KB_   3072            // expanded bf16 K (3 * 1024)
#define NIT   48              // k-iterations of BK=64 expanded bf16

// ---- scratch (__device__ globals) ------------------------------------------
// GEMM operands, tiled+swizzled: [tile][kstage][row 0..127][128B, chunk^=(row&7)]
__device__ __nv_bfloat16 gA[M_ * KB_];             // 24 MB activations
__device__ __nv_bfloat16 gBq[QKVN * (size_t)KB_];  // 18 MB W_qkv^T
__device__ __nv_bfloat16 gBp[C_ * (size_t)KB_];    // 6 MB  W_proj^T
// q/k/v, per-(bh, 64-token tile) contiguous 16KB blocks:
// [bh][tile][token 0..63][256B = hi(128)|lo(128), chunk^=(token&7)]
__device__ __nv_bfloat16 gQsp[B_ * H_ * T_ * 128];
__device__ __nv_bfloat16 gKsp[B_ * H_ * T_ * 128];
__device__ __nv_bfloat16 gVsp[B_ * H_ * T_ * 128];

// ============================================================================
// PTX helpers
// ============================================================================
__device__ __forceinline__ uint32_t smem_u32(const void* p) {
    uint32_t a;
    asm("{ .reg .u64 t; cvta.to.shared.u64 t, %1; cvt.u32.u64 %0, t; }" : "=r"(a) : "l"(p));
    return a;
}
__device__ __forceinline__ void bulk_cp(uint32_t dst, const void* src, uint32_t bytes,
                                        uint32_t mbar) {
    asm volatile(
        "cp.async.bulk.shared::cluster.global.mbarrier::complete_tx::bytes [%0], [%1], %2, [%3];"
        :: "r"(dst), "l"(src), "r"(bytes), "r"(mbar) : "memory");
}
#define MBAR_INIT(mbar, cnt)  asm volatile("mbarrier.init.shared.b64 [%0], %1;" :: "r"((uint32_t)(mbar)), "r"((uint32_t)(cnt)) : "memory")
#define MBAR_EXPECT_TX(mbar, bytes) asm volatile("mbarrier.arrive.expect_tx.shared.b64 _, [%0], %1;" :: "r"((uint32_t)(mbar)), "r"((uint32_t)(bytes)) : "memory")
#define MBAR_WAIT(mbar, parity) do {                                            \
    uint32_t _m = (uint32_t)(mbar); uint32_t _p = (uint32_t)(parity);           \
    asm volatile("{\n\t.reg .pred P1;\n\t"                                      \
        "WAIT_LOOP_%=:\n\t"                                                     \
        "mbarrier.try_wait.parity.acquire.cta.shared::cta.b64 P1, [%0], %1, 0x989680;\n\t" \
        "@P1 bra.uni WAIT_DONE_%=;\n\t"                                         \
        "bra.uni WAIT_LOOP_%=;\n\t"                                             \
        "WAIT_DONE_%=:\n\t}" :: "r"(_m), "r"(_p) : "memory");                   \
} while (0)

__device__ __forceinline__ void ldm4(uint32_t* r, uint32_t addr) {
    asm volatile("ldmatrix.sync.aligned.m8n8.x4.shared.b16 {%0,%1,%2,%3}, [%4];"
        : "=r"(r[0]), "=r"(r[1]), "=r"(r[2]), "=r"(r[3]) : "r"(addr));
}
__device__ __forceinline__ void ldm4t(uint32_t* r, uint32_t addr) {
    asm volatile("ldmatrix.sync.aligned.m8n8.x4.trans.shared.b16 {%0,%1,%2,%3}, [%4];"
        : "=r"(r[0]), "=r"(r[1]), "=r"(r[2]), "=r"(r[3]) : "r"(addr));
}
__device__ __forceinline__ void mma16816(float* c, const uint32_t* a, const uint32_t* b) {
    asm volatile(
        "mma.sync.aligned.m16n8k16.row.col.f32.bf16.bf16.f32 "
        "{%0,%1,%2,%3}, {%4,%5,%6,%7}, {%8,%9}, {%0,%1,%2,%3};"
        : "+f"(c[0]), "+f"(c[1]), "+f"(c[2]), "+f"(c[3])
        : "r"(a[0]), "r"(a[1]), "r"(a[2]), "r"(a[3]), "r"(b[0]), "r"(b[1]));
}
__device__ __forceinline__ uint32_t pack_bf2(__nv_bfloat16 lo, __nv_bfloat16 hi) {
    return ((uint32_t)__bfloat16_as_ushort(hi) << 16) | (uint32_t)__bfloat16_as_ushort(lo);
}

// ============================================================================
// Conversion kernels -> tiled+swizzled GEMM layouts (unchanged from R9)
// ============================================================================
__global__ __launch_bounds__(256) void convert_act(const float* __restrict__ x,
                                                   __nv_bfloat16* __restrict__ A) {
    int idx = blockIdx.x * 256 + threadIdx.x;
    int m  = idx >> 7;
    int kg = idx & 127;
    const float* p = x + (size_t)m * C_ + kg * 8;
    float4 v0 = *(const float4*)p;
    float4 v1 = *(const float4*)(p + 4);
    float v[8] = {v0.x, v0.y, v0.z, v0.w, v1.x, v1.y, v1.z, v1.w};
    union { __nv_bfloat16 h[24]; uint4 u[3]; } o;
    #pragma unroll
    for (int j = 0; j < 8; j++) {
        __nv_bfloat16 hi = __float2bfloat16(v[j]);
        __nv_bfloat16 lo = __float2bfloat16(v[j] - __bfloat162float(hi));
        o.h[3*j + 0] = hi; o.h[3*j + 1] = hi; o.h[3*j + 2] = lo;
    }
    char* base = (char*)A;
    #pragma unroll
    for (int j = 0; j < 3; j++) {
        int gc = kg * 3 + j;
        int st = gc >> 3;
        int pc = (gc & 7) ^ (m & 7);
        *(uint4*)(base + (((size_t)(m >> 7) * NIT + st) << 14)
                       + (m & 127) * 128 + pc * 16) = o.u[j];
    }
}

__global__ __launch_bounds__(128) void convert_w(const float* __restrict__ W,
                                                 __nv_bfloat16* __restrict__ Wp, int N) {
    __shared__ float s[32][33];
    int n0 = blockIdx.x * 32;
    int t = threadIdx.x;
    {
        int kr = t >> 3, nc = (t & 7) * 4;
        #pragma unroll
        for (int i = 0; i < 2; i++) {
            int k = kr + i * 16;
            float4 v = *(const float4*)(W + (size_t)(blockIdx.y * 32 + k) * N + n0 + nc);
            s[k][nc] = v.x; s[k][nc+1] = v.y; s[k][nc+2] = v.z; s[k][nc+3] = v.w;
        }
    }
    __syncthreads();
    int nl = t >> 2, kg = t & 3;
    union { __nv_bfloat16 h[24]; uint4 u[3]; } o;
    #pragma unroll
    for (int j = 0; j < 8; j++) {
        float v = s[kg * 8 + j][nl];
        __nv_bfloat16 hi = __float2bfloat16(v);
        __nv_bfloat16 lo = __float2bfloat16(v - __bfloat162float(hi));
        o.h[3*j + 0] = hi; o.h[3*j + 1] = lo; o.h[3*j + 2] = hi;
    }
    int n = n0 + nl;
    char* base = (char*)Wp;
    #pragma unroll
    for (int j = 0; j < 3; j++) {
        int gc = blockIdx.y * 12 + kg * 3 + j;
        int st = gc >> 3;
        int pc = (gc & 7) ^ (n & 7);
        *(uint4*)(base + (((size_t)(n >> 7) * NIT + st) << 14)
                       + (n & 127) * 128 + pc * 16) = o.u[j];
    }
}

// ============================================================================
// HMMA GEMM (R9 design): CTA 128x128, 4 warps 64x64, BK=64, bulk-copy ring.
// MODE 0: fp32 out + bias. MODE 1: writes swizzled q/k/v attention tiles.
// ============================================================================
#define STAGEB 32768
#define GSMEM  (3 * STAGEB + 64)   // 98368

template <int MODE>
__global__ __launch_bounds__(128, 2) void gemm_tc(
    const __nv_bfloat16* __restrict__ A, const __nv_bfloat16* __restrict__ Bw,
    const float* __restrict__ bias, float* __restrict__ Co, int Ntot,
    __nv_bfloat16* __restrict__ Qs, __nv_bfloat16* __restrict__ Ks,
    __nv_bfloat16* __restrict__ Vs)
{
    extern __shared__ char smemraw[];
    const uint32_t sb = smem_u32(smemraw);
    const uint32_t mb = sb + 3 * STAGEB;

    const int tid  = threadIdx.x;
    const int lane = tid & 31;
    const int wid  = tid >> 5;
    const int wr   = wid >> 1;
    const int wc   = wid & 1;

    const char* Ag = (const char*)A + ((size_t)blockIdx.y * NIT << 14);
    const char* Bg = (const char*)Bw + ((size_t)blockIdx.x * NIT << 14);

    if (tid == 0) {
        MBAR_INIT(mb + 0, 1); MBAR_INIT(mb + 8, 1); MBAR_INIT(mb + 16, 1);
    }
    __syncthreads();

    auto issue = [&](int s) {
        if (tid == 0) {
            int buf = s % 3;
            uint32_t mbar = mb + (uint32_t)buf * 8;
            uint32_t dA = sb + (uint32_t)buf * STAGEB;
            MBAR_EXPECT_TX(mbar, 32768);
            bulk_cp(dA,          Ag + ((size_t)s << 14), 16384, mbar);
            bulk_cp(dA + 16384u, Bg + ((size_t)s << 14), 16384, mbar);
        }
    };
    issue(0); issue(1); issue(2);

    float acc[4][8][4];
    #pragma unroll
    for (int mt = 0; mt < 4; mt++)
        #pragma unroll
        for (int nt = 0; nt < 8; nt++)
            #pragma unroll
            for (int q = 0; q < 4; q++) acc[mt][nt][q] = 0.f;

    const int arow = (lane & 7) + ((lane >> 3) & 1) * 8;
    const int achk = lane >> 4;
    const int brw  = (lane & 7) + ((lane >> 4) & 1) * 8;
    const int bchk = (lane >> 3) & 1;
    const int xa = arow & 7, xb = brw & 7;

    #pragma unroll 1
    for (int s = 0; s < NIT; s++) {
        const int buf = s % 3;
        MBAR_WAIT(mb + (uint32_t)buf * 8, (s / 3) & 1);
        const uint32_t bA = sb + (uint32_t)buf * STAGEB;
        const uint32_t bB = bA + 16384u;

        #pragma unroll
        for (int ks = 0; ks < 4; ks++) {
            uint32_t afr[4][4], bfr[4][4];
            const int ca = ((2 * ks + achk) ^ xa) * 16;
            const int cb = ((2 * ks + bchk) ^ xb) * 16;
            #pragma unroll
            for (int mt = 0; mt < 4; mt++)
                ldm4(afr[mt], bA + (uint32_t)((wr * 64 + mt * 16 + arow) * 128 + ca));
            #pragma unroll
            for (int n2 = 0; n2 < 4; n2++)
                ldm4(bfr[n2], bB + (uint32_t)((wc * 64 + n2 * 16 + brw) * 128 + cb));
            #pragma unroll
            for (int mt = 0; mt < 4; mt++)
                #pragma unroll
                for (int nt = 0; nt < 8; nt++)
                    mma16816(acc[mt][nt], afr[mt], &bfr[nt >> 1][(nt & 1) * 2]);
        }
        __syncthreads();
        if (s + 3 < NIT) issue(s + 3);
    }

    const int brow = blockIdx.y * 128;
    const int bcol = blockIdx.x * 128;
    const int crow = lane >> 2;
    const int ccol = (lane & 3) * 2;

    if (MODE == 0) {
        #pragma unroll
        for (int nt = 0; nt < 8; nt++) {
            int col = bcol + wc * 64 + nt * 8 + ccol;
            float2 bi = *(const float2*)(bias + col);
            #pragma unroll
            for (int mt = 0; mt < 4; mt++) {
                int row = brow + wr * 64 + mt * 16 + crow;
                float2 v0 = make_float2(acc[mt][nt][0] + bi.x, acc[mt][nt][1] + bi.y);
                float2 v1 = make_float2(acc[mt][nt][2] + bi.x, acc[mt][nt][3] + bi.y);
                *(float2*)(Co + (size_t)row * Ntot + col)       = v0;
                *(float2*)(Co + (size_t)(row + 8) * Ntot + col) = v1;
            }
        }
    } else {
        // write swizzled 16KB attention tiles: [bh][tile][tt][256B, chunk^=(tt&7)]
        const int p  = bcol >> 10;
        __nv_bfloat16* outb = (p == 0) ? Qs : ((p == 1) ? Ks : Vs);
        const float sc = (p == 0) ? 0.125f : 1.f;
        const int hh = ((bcol + wc * 64) >> 6) & 15;
        #pragma unroll
        for (int nt = 0; nt < 8; nt++) {
            int gcol = bcol + wc * 64 + nt * 8 + ccol;
            float2 bi = *(const float2*)(bias + gcol);
            int d = nt * 8 + ccol;
            int o1 = 2 * d;          // hi word byte offset in 256B row
            int o2 = 128 + 2 * d;    // lo word
            #pragma unroll
            for (int mt = 0; mt < 4; mt++) {
                int grow = brow + wr * 64 + mt * 16 + crow;
                #pragma unroll
                for (int half = 0; half < 2; half++) {
                    int m = grow + half * 8;
                    int bb = m >> 11, t = m & 2047;
                    float f0 = (acc[mt][nt][half * 2 + 0] + bi.x) * sc;
                    float f1 = (acc[mt][nt][half * 2 + 1] + bi.y) * sc;
                    __nv_bfloat16 h0 = __float2bfloat16(f0);
                    __nv_bfloat16 l0 = __float2bfloat16(f0 - __bfloat162float(h0));
                    __nv_bfloat16 h1 = __float2bfloat16(f1);
                    __nv_bfloat16 l1 = __float2bfloat16(f1 - __bfloat162float(h1));
                    int tt = t & 63;
                    char* tb = (char*)outb
                        + (((size_t)((bb * H_ + hh) * 32 + (t >> 6))) << 14)
                        + tt * 256;
                    *(uint32_t*)(tb + (((o1 >> 4) ^ (tt & 7)) << 4) + (o1 & 15))
                        = pack_bf2(h0, h1);
                    *(uint32_t*)(tb + (((o2 >> 4) ^ (tt & 7)) << 4) + (o2 & 15))
                        = pack_bf2(l0, l1);
                }
            }
        }
    }
}

// ============================================================================
// HMMA flash attention: bulk-copy staged swizzled 16KB tiles, mbarrier ring.
// smem: Q(16K) | K0 | V0 | K1 | V1 (16K each) | P (64*ASTR) | mbars
// ============================================================================
#define ASTR  272
#define QKV_TILE 16384
#define PS_OFF  (5 * QKV_TILE)
#define AMB_OFF (PS_OFF + 64 * ASTR)
#define ATTN_SMEM (AMB_OFF + 64)    // 99392

__global__ __launch_bounds__(128, 2) void attn_mma(
    const __nv_bfloat16* __restrict__ Qsp, const __nv_bfloat16* __restrict__ Ksp,
    const __nv_bfloat16* __restrict__ Vsp, __nv_bfloat16* __restrict__ Aout)
{
    extern __shared__ char smbuf[];
    const uint32_t sb   = smem_u32(smbuf);
    const uint32_t qs_b = sb;
    const uint32_t ps_b = sb + PS_OFF;
    const uint32_t mb   = sb + AMB_OFF;
    char* Psc = smbuf + PS_OFF;

    const int tid  = threadIdx.x;
    const int lane = tid & 31;
    const int wid  = tid >> 5;
    const int qt   = (int)gridDim.x - 1 - (int)blockIdx.x;
    const int bh   = blockIdx.y;
    const int b = bh >> 4, h = bh & 15;

    const char* Qgc = (const char*)Qsp + ((size_t)(bh * 32 + qt) << 14);
    const char* Kgc = (const char*)Ksp + ((size_t)(bh * 32) << 14);
    const char* Vgc = (const char*)Vsp + ((size_t)(bh * 32) << 14);

    if (tid == 0) { MBAR_INIT(mb + 0, 1); MBAR_INIT(mb + 8, 1); }
    __syncthreads();

    // prologue: Q + K0 + V0 on bar0; K1 + V1 on bar1
    if (tid == 0) {
        MBAR_EXPECT_TX(mb + 0, 3 * QKV_TILE);
        bulk_cp(qs_b, Qgc, QKV_TILE, mb + 0);
        bulk_cp(sb + 1 * QKV_TILE, Kgc, QKV_TILE, mb + 0);
        bulk_cp(sb + 2 * QKV_TILE, Vgc, QKV_TILE, mb + 0);
        if (qt >= 1) {
            MBAR_EXPECT_TX(mb + 8, 2 * QKV_TILE);
            bulk_cp(sb + 3 * QKV_TILE, Kgc + QKV_TILE, QKV_TILE, mb + 8);
            bulk_cp(sb + 4 * QKV_TILE, Vgc + QKV_TILE, QKV_TILE, mb + 8);
        }
    }

    // fragment lane maps
    const int arow = (lane & 7) + ((lane >> 3) & 1) * 8;
    const int achk = lane >> 4;
    const int brw  = (lane & 7) + ((lane >> 4) & 1) * 8;
    const int bchk = (lane >> 3) & 1;
    const int tq = wid * 16 + arow;     // Q token row
    const int xq = tq & 7;
    const int xk = brw & 7;
    const int xv = arow & 7;
    const uint32_t aoffP = (uint32_t)(tq * ASTR + achk * 16);   // P tile (padded)

    float m0 = -1e30f, m1 = -1e30f, l0 = 0.f, l1 = 0.f;
    float accO[8][4];
    #pragma unroll
    for (int nt = 0; nt < 8; nt++)
        #pragma unroll
        for (int q = 0; q < 4; q++) accO[nt][q] = 0.f;

    const int r0 = lane >> 2;
    const int c0 = (lane & 3) * 2;
    const int row0 = wid * 16 + r0;

    #pragma unroll 1
    for (int kt = 0; kt <= qt; kt++) {
        MBAR_WAIT(mb + (uint32_t)(kt & 1) * 8, (kt >> 1) & 1);
        const uint32_t kbuf = sb + (uint32_t)(1 + 2 * (kt & 1)) * QKV_TILE;
        const uint32_t vbuf = kbuf + QKV_TILE;

        // ---- S = Q @ K^T (3-pass: hi*hi, hi*lo, lo*hi)
        float accS[8][4];
        #pragma unroll
        for (int nt = 0; nt < 8; nt++)
            #pragma unroll
            for (int q = 0; q < 4; q++) accS[nt][q] = 0.f;
        #pragma unroll
        for (int pass = 0; pass < 3; pass++) {
            const int aadd = (pass == 2) ? 8 : 0;
            const int badd = (pass == 1) ? 8 : 0;
            #pragma unroll
            for (int ks = 0; ks < 4; ks++) {
                uint32_t afr[4], bfr[4][4];
                ldm4(afr, qs_b + (uint32_t)(tq * 256 +
                     (((2 * ks + achk + aadd) ^ xq) << 4)));
                #pragma unroll
                for (int n2 = 0; n2 < 4; n2++)
                    ldm4(bfr[n2], kbuf + (uint32_t)((n2 * 16 + brw) * 256 +
                         (((2 * ks + bchk + badd) ^ xk) << 4)));
                #pragma unroll
                for (int nt = 0; nt < 8; nt++)
                    mma16816(accS[nt], afr, &bfr[nt >> 1][(nt & 1) * 2]);
            }
        }

        if (kt == qt) {
            #pragma unroll
            for (int nt = 0; nt < 8; nt++) {
                int col = nt * 8 + c0;
                if (col     > row0)     accS[nt][0] = -1e30f;
                if (col + 1 > row0)     accS[nt][1] = -1e30f;
                if (col     > row0 + 8) accS[nt][2] = -1e30f;
                if (col + 1 > row0 + 8) accS[nt][3] = -1e30f;
            }
        }

        // ---- online softmax + write P (hi/lo into padded Ps)
        {
            float mx0 = -1e30f, mx1 = -1e30f;
            #pragma unroll
            for (int nt = 0; nt < 8; nt++) {
                mx0 = fmaxf(mx0, fmaxf(accS[nt][0], accS[nt][1]));
                mx1 = fmaxf(mx1, fmaxf(accS[nt][2], accS[nt][3]));
            }
            mx0 = fmaxf(mx0, __shfl_xor_sync(0xffffffffu, mx0, 1));
            mx0 = fmaxf(mx0, __shfl_xor_sync(0xffffffffu, mx0, 2));
            mx1 = fmaxf(mx1, __shfl_xor_sync(0xffffffffu, mx1, 1));
            mx1 = fmaxf(mx1, __shfl_xor_sync(0xffffffffu, mx1, 2));

            float mn0 = fmaxf(m0, mx0), mn1 = fmaxf(m1, mx1);
            float al0 = __expf(m0 - mn0), al1 = __expf(m1 - mn1);
            m0 = mn0; m1 = mn1;

            char* prow0 = Psc + (wid * 16 + r0) * ASTR + c0 * 2;
            char* prow1 = prow0 + 8 * ASTR;
            float sum0 = 0.f, sum1 = 0.f;
            #pragma unroll
            for (int nt = 0; nt < 8; nt++) {
                float p0 = __expf(accS[nt][0] - mn0);
                float p1 = __expf(accS[nt][1] - mn0);
                float p2 = __expf(accS[nt][2] - mn1);
                float p3 = __expf(accS[nt][3] - mn1);
                sum0 += p0 + p1; sum1 += p2 + p3;
                __nv_bfloat16 h0 = __float2bfloat16(p0), h1 = __float2bfloat16(p1);
                __nv_bfloat16 h2 = __float2bfloat16(p2), h3 = __float2bfloat16(p3);
                __nv_bfloat16 g0 = __float2bfloat16(p0 - __bfloat162float(h0));
                __nv_bfloat16 g1 = __float2bfloat16(p1 - __bfloat162float(h1));
                __nv_bfloat16 g2 = __float2bfloat16(p2 - __bfloat162float(h2));
                __nv_bfloat16 g3 = __float2bfloat16(p3 - __bfloat162float(h3));
                *(uint32_t*)(prow0 + nt * 16)        = pack_bf2(h0, h1);
                *(uint32_t*)(prow0 + 128 + nt * 16)  = pack_bf2(g0, g1);
                *(uint32_t*)(prow1 + nt * 16)        = pack_bf2(h2, h3);
                *(uint32_t*)(prow1 + 128 + nt * 16)  = pack_bf2(g2, g3);
            }
            sum0 += __shfl_xor_sync(0xffffffffu, sum0, 1);
            sum0 += __shfl_xor_sync(0xffffffffu, sum0, 2);
            sum1 += __shfl_xor_sync(0xffffffffu, sum1, 1);
            sum1 += __shfl_xor_sync(0xffffffffu, sum1, 2);
            l0 = l0 * al0 + sum0;
            l1 = l1 * al1 + sum1;

            #pragma unroll
            for (int nt = 0; nt < 8; nt++) {
                accO[nt][0] *= al0; accO[nt][1] *= al0;
                accO[nt][2] *= al1; accO[nt][3] *= al1;
            }
        }
        __syncwarp();

        // ---- O += P @ V (3-pass; V via ldmatrix.trans, swizzled tile)
        #pragma unroll
        for (int pass = 0; pass < 3; pass++) {
            const uint32_t aadd = (pass == 2) ? 128u : 0u;   // P lo
            const int badd = (pass == 1) ? 8 : 0;            // V lo
            #pragma unroll
            for (int ks = 0; ks < 4; ks++) {
                uint32_t pfr[4], vfr[4][4];
                ldm4(pfr, ps_b + aoffP + aadd + ks * 32);
                #pragma unroll
                for (int n2 = 0; n2 < 4; n2++)
                    ldm4t(vfr[n2], vbuf + (uint32_t)((ks * 16 + arow) * 256 +
                          (((n2 * 2 + achk + badd) ^ xv) << 4)));
                #pragma unroll
                for (int nt = 0; nt < 8; nt++)
                    mma16816(accO[nt], pfr, &vfr[nt >> 1][(nt & 1) * 2]);
            }
        }

        __syncthreads();   // all warps done with this buffer + P
        if (tid == 0 && kt + 2 <= qt) {
            uint32_t mbar = mb + (uint32_t)(kt & 1) * 8;
            uint32_t nb = sb + (uint32_t)(1 + 2 * (kt & 1)) * QKV_TILE;
            MBAR_EXPECT_TX(mbar, 2 * QKV_TILE);
            bulk_cp(nb,            Kgc + ((size_t)(kt + 2) << 14), QKV_TILE, mbar);
            bulk_cp(nb + QKV_TILE, Vgc + ((size_t)(kt + 2) << 14), QKV_TILE, mbar);
        }
    }

    // ---- normalize + write [hi,hi,lo] triplets into TILED-SWIZZLED gA
    float inv0 = 1.f / l0, inv1 = 1.f / l1;
    int grow = qt * 64 + wid * 16 + r0;
    size_t m0r = (size_t)b * T_ + grow;
    size_t m1r = m0r + 8;
    char* Ac = (char*)Aout;
    auto writeWord = [&](size_t m, int o, uint32_t val) {
        int gc = o >> 4, st = gc >> 3, pc = (gc & 7) ^ ((int)m & 7);
        *(uint32_t*)(Ac + (((m >> 7) * NIT + st) << 14)
                        + (m & 127) * 128 + pc * 16 + (o & 15)) = val;
    };
    #pragma unroll
    for (int nt = 0; nt < 8; nt++) {
        int d = nt * 8 + c0;
        int o = (h * D_ + d) * 6;
        float f0 = accO[nt][0] * inv0, f1 = accO[nt][1] * inv0;
        float f2 = accO[nt][2] * inv1, f3 = accO[nt][3] * inv1;
        __nv_bfloat16 h0 = __float2bfloat16(f0);
        __nv_bfloat16 e0 = __float2bfloat16(f0 - __bfloat162float(h0));
        __nv_bfloat16 h1 = __float2bfloat16(f1);
        __nv_bfloat16 e1 = __float2bfloat16(f1 - __bfloat162float(h1));
        __nv_bfloat16 h2 = __float2bfloat16(f2);
        __nv_bfloat16 e2 = __float2bfloat16(f2 - __bfloat162float(h2));
        __nv_bfloat16 h3 = __float2bfloat16(f3);
        __nv_bfloat16 e3 = __float2bfloat16(f3 - __bfloat162float(h3));
        writeWord(m0r, o + 0, pack_bf2(h0, h0));
        writeWord(m0r, o + 4, pack_bf2(e0, h1));
        writeWord(m0r, o + 8, pack_bf2(h1, e1));
        writeWord(m1r, o + 0, pack_bf2(h2, h2));
        writeWord(m1r, o + 4, pack_bf2(e2, h3));
        writeWord(m1r, o + 8, pack_bf2(h3, e3));
    }
}

// ---------------------------------------------------------------------------
extern "C" void kernel_launch(void* const* d_in, const int* in_sizes, int n_in,
                              void* d_out, int out_size)
{
    const float* x     = (const float*)d_in[0];
    const float* Wqkv  = (const float*)d_in[1];
    const float* bqkv  = (const float*)d_in[2];
    const float* Wproj = (const float*)d_in[3];
    const float* bproj = (const float*)d_in[4];
    float* out = (float*)d_out;

    __nv_bfloat16 *gA_p = nullptr, *gBq_p = nullptr, *gBp_p = nullptr;
    __nv_bfloat16 *q_p = nullptr, *k_p = nullptr, *v_p = nullptr;
    cudaGetSymbolAddress((void**)&gA_p,  gA);
    cudaGetSymbolAddress((void**)&gBq_p, gBq);
    cudaGetSymbolAddress((void**)&gBp_p, gBp);
    cudaGetSymbolAddress((void**)&q_p,   gQsp);
    cudaGetSymbolAddress((void**)&k_p,   gKsp);
    cudaGetSymbolAddress((void**)&v_p,   gVsp);

    cudaFuncSetAttribute(attn_mma,
                         cudaFuncAttributeMaxDynamicSharedMemorySize, ATTN_SMEM);
    cudaFuncSetAttribute(gemm_tc<0>,
                         cudaFuncAttributeMaxDynamicSharedMemorySize, GSMEM);
    cudaFuncSetAttribute(gemm_tc<1>,
                         cudaFuncAttributeMaxDynamicSharedMemorySize, GSMEM);

    // conversions (tiled+swizzled outputs)
    convert_w<<<dim3(QKVN / 32, C_ / 32), 128>>>(Wqkv, gBq_p, QKVN);
    convert_w<<<dim3(C_ / 32, C_ / 32), 128>>>(Wproj, gBp_p, C_);
    convert_act<<<(M_ * C_ / 8) / 256, 256>>>(x, gA_p);

    // 1) QKV projection, fused swizzled-tile q/k/v epilogue
    gemm_tc<1><<<dim3(QKVN / 128, M_ / 128), 128, GSMEM>>>(
        gA_p, gBq_p, bqkv, nullptr, QKVN, q_p, k_p, v_p);

    // 2) causal flash attention; epilogue writes proj-input triplets into gA
    attn_mma<<<dim3(T_ / 64, B_ * H_), 128, ATTN_SMEM>>>(q_p, k_p, v_p, gA_p);

    // 3) output projection
    gemm_tc<0><<<dim3(C_ / 128, M_ / 128), 128, GSMEM>>>(
        gA_p, gBp_p, bproj, out, C_, nullptr, nullptr, nullptr);
}

// round 12
// speedup vs baseline: 1.0037x; 1.0037x over previous
#include <cuda_runtime.h>
#include <cuda_bf16.h>
#include <cstdint>
#include <math.h>

#define B_    2
#define T_    2048
#define C_    1024
#define H_    16
#define D_    64
#define M_    4096
#define QKVN  3072
#define KB_   3072            // expanded bf16 K (3 * 1024)
#define NIT   48              // k-iterations of BK=64 expanded bf16

// ---- scratch (__device__ globals) ------------------------------------------
// GEMM operands, tiled+swizzled: [tile][kstage][row 0..127][128B, chunk^=(row&7)]
__device__ __nv_bfloat16 gA[M_ * KB_];             // 24 MB activations
__device__ __nv_bfloat16 gBq[QKVN * (size_t)KB_];  // 18 MB W_qkv^T
__device__ __nv_bfloat16 gBp[C_ * (size_t)KB_];    // 6 MB  W_proj^T
// q/k/v, per-(bh, 64-token tile) contiguous 16KB blocks:
// [bh][tile][token 0..63][256B = hi(128)|lo(128), chunk^=(token&7)]
__device__ __nv_bfloat16 gQsp[B_ * H_ * T_ * 128];
__device__ __nv_bfloat16 gKsp[B_ * H_ * T_ * 128];
__device__ __nv_bfloat16 gVsp[B_ * H_ * T_ * 128];

// ============================================================================
// PTX helpers
// ============================================================================
__device__ __forceinline__ uint32_t smem_u32(const void* p) {
    uint32_t a;
    asm("{ .reg .u64 t; cvta.to.shared.u64 t, %1; cvt.u32.u64 %0, t; }" : "=r"(a) : "l"(p));
    return a;
}
__device__ __forceinline__ void bulk_cp(uint32_t dst, const void* src, uint32_t bytes,
                                        uint32_t mbar) {
    asm volatile(
        "cp.async.bulk.shared::cluster.global.mbarrier::complete_tx::bytes [%0], [%1], %2, [%3];"
        :: "r"(dst), "l"(src), "r"(bytes), "r"(mbar) : "memory");
}
#define MBAR_INIT(mbar, cnt)  asm volatile("mbarrier.init.shared.b64 [%0], %1;" :: "r"((uint32_t)(mbar)), "r"((uint32_t)(cnt)) : "memory")
#define MBAR_EXPECT_TX(mbar, bytes) asm volatile("mbarrier.arrive.expect_tx.shared.b64 _, [%0], %1;" :: "r"((uint32_t)(mbar)), "r"((uint32_t)(bytes)) : "memory")
#define MBAR_WAIT(mbar, parity) do {                                            \
    uint32_t _m = (uint32_t)(mbar); uint32_t _p = (uint32_t)(parity);           \
    asm volatile("{\n\t.reg .pred P1;\n\t"                                      \
        "WAIT_LOOP_%=:\n\t"                                                     \
        "mbarrier.try_wait.parity.acquire.cta.shared::cta.b64 P1, [%0], %1, 0x989680;\n\t" \
        "@P1 bra.uni WAIT_DONE_%=;\n\t"                                         \
        "bra.uni WAIT_LOOP_%=;\n\t"                                             \
        "WAIT_DONE_%=:\n\t}" :: "r"(_m), "r"(_p) : "memory");                   \
} while (0)

__device__ __forceinline__ void ldm4(uint32_t* r, uint32_t addr) {
    asm volatile("ldmatrix.sync.aligned.m8n8.x4.shared.b16 {%0,%1,%2,%3}, [%4];"
        : "=r"(r[0]), "=r"(r[1]), "=r"(r[2]), "=r"(r[3]) : "r"(addr));
}
__device__ __forceinline__ void ldm4t(uint32_t* r, uint32_t addr) {
    asm volatile("ldmatrix.sync.aligned.m8n8.x4.trans.shared.b16 {%0,%1,%2,%3}, [%4];"
        : "=r"(r[0]), "=r"(r[1]), "=r"(r[2]), "=r"(r[3]) : "r"(addr));
}
__device__ __forceinline__ void mma16816(float* c, const uint32_t* a, const uint32_t* b) {
    asm volatile(
        "mma.sync.aligned.m16n8k16.row.col.f32.bf16.bf16.f32 "
        "{%0,%1,%2,%3}, {%4,%5,%6,%7}, {%8,%9}, {%0,%1,%2,%3};"
        : "+f"(c[0]), "+f"(c[1]), "+f"(c[2]), "+f"(c[3])
        : "r"(a[0]), "r"(a[1]), "r"(a[2]), "r"(a[3]), "r"(b[0]), "r"(b[1]));
}
__device__ __forceinline__ uint32_t pack_bf2(__nv_bfloat16 lo, __nv_bfloat16 hi) {
    return ((uint32_t)__bfloat16_as_ushort(hi) << 16) | (uint32_t)__bfloat16_as_ushort(lo);
}

// ============================================================================
// Conversion kernels -> tiled+swizzled GEMM layouts (unchanged from R9)
// ============================================================================
__global__ __launch_bounds__(256) void convert_act(const float* __restrict__ x,
                                                   __nv_bfloat16* __restrict__ A) {
    int idx = blockIdx.x * 256 + threadIdx.x;
    int m  = idx >> 7;
    int kg = idx & 127;
    const float* p = x + (size_t)m * C_ + kg * 8;
    float4 v0 = *(const float4*)p;
    float4 v1 = *(const float4*)(p + 4);
    float v[8] = {v0.x, v0.y, v0.z, v0.w, v1.x, v1.y, v1.z, v1.w};
    union { __nv_bfloat16 h[24]; uint4 u[3]; } o;
    #pragma unroll
    for (int j = 0; j < 8; j++) {
        __nv_bfloat16 hi = __float2bfloat16(v[j]);
        __nv_bfloat16 lo = __float2bfloat16(v[j] - __bfloat162float(hi));
        o.h[3*j + 0] = hi; o.h[3*j + 1] = hi; o.h[3*j + 2] = lo;
    }
    char* base = (char*)A;
    #pragma unroll
    for (int j = 0; j < 3; j++) {
        int gc = kg * 3 + j;
        int st = gc >> 3;
        int pc = (gc & 7) ^ (m & 7);
        *(uint4*)(base + (((size_t)(m >> 7) * NIT + st) << 14)
                       + (m & 127) * 128 + pc * 16) = o.u[j];
    }
}

__global__ __launch_bounds__(128) void convert_w(const float* __restrict__ W,
                                                 __nv_bfloat16* __restrict__ Wp, int N) {
    __shared__ float s[32][33];
    int n0 = blockIdx.x * 32;
    int t = threadIdx.x;
    {
        int kr = t >> 3, nc = (t & 7) * 4;
        #pragma unroll
        for (int i = 0; i < 2; i++) {
            int k = kr + i * 16;
            float4 v = *(const float4*)(W + (size_t)(blockIdx.y * 32 + k) * N + n0 + nc);
            s[k][nc] = v.x; s[k][nc+1] = v.y; s[k][nc+2] = v.z; s[k][nc+3] = v.w;
        }
    }
    __syncthreads();
    int nl = t >> 2, kg = t & 3;
    union { __nv_bfloat16 h[24]; uint4 u[3]; } o;
    #pragma unroll
    for (int j = 0; j < 8; j++) {
        float v = s[kg * 8 + j][nl];
        __nv_bfloat16 hi = __float2bfloat16(v);
        __nv_bfloat16 lo = __float2bfloat16(v - __bfloat162float(hi));
        o.h[3*j + 0] = hi; o.h[3*j + 1] = lo; o.h[3*j + 2] = hi;
    }
    int n = n0 + nl;
    char* base = (char*)Wp;
    #pragma unroll
    for (int j = 0; j < 3; j++) {
        int gc = blockIdx.y * 12 + kg * 3 + j;
        int st = gc >> 3;
        int pc = (gc & 7) ^ (n & 7);
        *(uint4*)(base + (((size_t)(n >> 7) * NIT + st) << 14)
                       + (n & 127) * 128 + pc * 16) = o.u[j];
    }
}

// ============================================================================
// HMMA GEMM (R9 design): CTA 128x128, 4 warps 64x64, BK=64, bulk-copy ring.
// MODE 0: fp32 out + bias. MODE 1: writes swizzled q/k/v attention tiles.
// ============================================================================
#define STAGEB 32768
#define GSMEM  (3 * STAGEB + 64)   // 98368

template <int MODE>
__global__ __launch_bounds__(128, 2) void gemm_tc(
    const __nv_bfloat16* __restrict__ A, const __nv_bfloat16* __restrict__ Bw,
    const float* __restrict__ bias, float* __restrict__ Co, int Ntot,
    __nv_bfloat16* __restrict__ Qs, __nv_bfloat16* __restrict__ Ks,
    __nv_bfloat16* __restrict__ Vs)
{
    extern __shared__ char smemraw[];
    const uint32_t sb = smem_u32(smemraw);
    const uint32_t mb = sb + 3 * STAGEB;

    const int tid  = threadIdx.x;
    const int lane = tid & 31;
    const int wid  = tid >> 5;
    const int wr   = wid >> 1;
    const int wc   = wid & 1;

    const char* Ag = (const char*)A + ((size_t)blockIdx.y * NIT << 14);
    const char* Bg = (const char*)Bw + ((size_t)blockIdx.x * NIT << 14);

    if (tid == 0) {
        MBAR_INIT(mb + 0, 1); MBAR_INIT(mb + 8, 1); MBAR_INIT(mb + 16, 1);
    }
    __syncthreads();

    auto issue = [&](int s) {
        if (tid == 0) {
            int buf = s % 3;
            uint32_t mbar = mb + (uint32_t)buf * 8;
            uint32_t dA = sb + (uint32_t)buf * STAGEB;
            MBAR_EXPECT_TX(mbar, 32768);
            bulk_cp(dA,          Ag + ((size_t)s << 14), 16384, mbar);
            bulk_cp(dA + 16384u, Bg + ((size_t)s << 14), 16384, mbar);
        }
    };
    issue(0); issue(1); issue(2);

    float acc[4][8][4];
    #pragma unroll
    for (int mt = 0; mt < 4; mt++)
        #pragma unroll
        for (int nt = 0; nt < 8; nt++)
            #pragma unroll
            for (int q = 0; q < 4; q++) acc[mt][nt][q] = 0.f;

    const int arow = (lane & 7) + ((lane >> 3) & 1) * 8;
    const int achk = lane >> 4;
    const int brw  = (lane & 7) + ((lane >> 4) & 1) * 8;
    const int bchk = (lane >> 3) & 1;
    const int xa = arow & 7, xb = brw & 7;

    #pragma unroll 1
    for (int s = 0; s < NIT; s++) {
        const int buf = s % 3;
        MBAR_WAIT(mb + (uint32_t)buf * 8, (s / 3) & 1);
        const uint32_t bA = sb + (uint32_t)buf * STAGEB;
        const uint32_t bB = bA + 16384u;

        #pragma unroll
        for (int ks = 0; ks < 4; ks++) {
            uint32_t afr[4][4], bfr[4][4];
            const int ca = ((2 * ks + achk) ^ xa) * 16;
            const int cb = ((2 * ks + bchk) ^ xb) * 16;
            #pragma unroll
            for (int mt = 0; mt < 4; mt++)
                ldm4(afr[mt], bA + (uint32_t)((wr * 64 + mt * 16 + arow) * 128 + ca));
            #pragma unroll
            for (int n2 = 0; n2 < 4; n2++)
                ldm4(bfr[n2], bB + (uint32_t)((wc * 64 + n2 * 16 + brw) * 128 + cb));
            #pragma unroll
            for (int mt = 0; mt < 4; mt++)
                #pragma unroll
                for (int nt = 0; nt < 8; nt++)
                    mma16816(acc[mt][nt], afr[mt], &bfr[nt >> 1][(nt & 1) * 2]);
        }
        __syncthreads();
        if (s + 3 < NIT) issue(s + 3);
    }

    const int brow = blockIdx.y * 128;
    const int bcol = blockIdx.x * 128;
    const int crow = lane >> 2;
    const int ccol = (lane & 3) * 2;

    if (MODE == 0) {
        #pragma unroll
        for (int nt = 0; nt < 8; nt++) {
            int col = bcol + wc * 64 + nt * 8 + ccol;
            float2 bi = *(const float2*)(bias + col);
            #pragma unroll
            for (int mt = 0; mt < 4; mt++) {
                int row = brow + wr * 64 + mt * 16 + crow;
                float2 v0 = make_float2(acc[mt][nt][0] + bi.x, acc[mt][nt][1] + bi.y);
                float2 v1 = make_float2(acc[mt][nt][2] + bi.x, acc[mt][nt][3] + bi.y);
                *(float2*)(Co + (size_t)row * Ntot + col)       = v0;
                *(float2*)(Co + (size_t)(row + 8) * Ntot + col) = v1;
            }
        }
    } else {
        // write swizzled 16KB attention tiles: [bh][tile][tt][256B, chunk^=(tt&7)]
        const int p  = bcol >> 10;
        __nv_bfloat16* outb = (p == 0) ? Qs : ((p == 1) ? Ks : Vs);
        const float sc = (p == 0) ? 0.125f : 1.f;
        const int hh = ((bcol + wc * 64) >> 6) & 15;
        #pragma unroll
        for (int nt = 0; nt < 8; nt++) {
            int gcol = bcol + wc * 64 + nt * 8 + ccol;
            float2 bi = *(const float2*)(bias + gcol);
            int d = nt * 8 + ccol;
            int o1 = 2 * d;          // hi word byte offset in 256B row
            int o2 = 128 + 2 * d;    // lo word
            #pragma unroll
            for (int mt = 0; mt < 4; mt++) {
                int grow = brow + wr * 64 + mt * 16 + crow;
                #pragma unroll
                for (int half = 0; half < 2; half++) {
                    int m = grow + half * 8;
                    int bb = m >> 11, t = m & 2047;
                    float f0 = (acc[mt][nt][half * 2 + 0] + bi.x) * sc;
                    float f1 = (acc[mt][nt][half * 2 + 1] + bi.y) * sc;
                    __nv_bfloat16 h0 = __float2bfloat16(f0);
                    __nv_bfloat16 l0 = __float2bfloat16(f0 - __bfloat162float(h0));
                    __nv_bfloat16 h1 = __float2bfloat16(f1);
                    __nv_bfloat16 l1 = __float2bfloat16(f1 - __bfloat162float(h1));
                    int tt = t & 63;
                    char* tb = (char*)outb
                        + (((size_t)((bb * H_ + hh) * 32 + (t >> 6))) << 14)
                        + tt * 256;
                    *(uint32_t*)(tb + (((o1 >> 4) ^ (tt & 7)) << 4) + (o1 & 15))
                        = pack_bf2(h0, h1);
                    *(uint32_t*)(tb + (((o2 >> 4) ^ (tt & 7)) << 4) + (o2 & 15))
                        = pack_bf2(l0, l1);
                }
            }
        }
    }
}

// ============================================================================
// HMMA flash attention: bulk-copy staged swizzled 16KB tiles, mbarrier ring.
// smem: Q(16K) | K0 | V0 | K1 | V1 (16K each) | P (64*ASTR) | mbars
// ============================================================================
#define ASTR  272
#define QKV_TILE 16384
#define PS_OFF  (5 * QKV_TILE)
#define AMB_OFF (PS_OFF + 64 * ASTR)
#define ATTN_SMEM (AMB_OFF + 64)    // 99392

__global__ __launch_bounds__(128, 2) void attn_mma(
    const __nv_bfloat16* __restrict__ Qsp, const __nv_bfloat16* __restrict__ Ksp,
    const __nv_bfloat16* __restrict__ Vsp, __nv_bfloat16* __restrict__ Aout)
{
    extern __shared__ char smbuf[];
    const uint32_t sb   = smem_u32(smbuf);
    const uint32_t qs_b = sb;
    const uint32_t ps_b = sb + PS_OFF;
    const uint32_t mb   = sb + AMB_OFF;
    char* Psc = smbuf + PS_OFF;

    const int tid  = threadIdx.x;
    const int lane = tid & 31;
    const int wid  = tid >> 5;
    const int qt   = (int)gridDim.x - 1 - (int)blockIdx.x;
    const int bh   = blockIdx.y;
    const int b = bh >> 4, h = bh & 15;

    const char* Qgc = (const char*)Qsp + ((size_t)(bh * 32 + qt) << 14);
    const char* Kgc = (const char*)Ksp + ((size_t)(bh * 32) << 14);
    const char* Vgc = (const char*)Vsp + ((size_t)(bh * 32) << 14);

    if (tid == 0) { MBAR_INIT(mb + 0, 1); MBAR_INIT(mb + 8, 1); }
    __syncthreads();

    // prologue: Q + K0 + V0 on bar0; K1 + V1 on bar1
    if (tid == 0) {
        MBAR_EXPECT_TX(mb + 0, 3 * QKV_TILE);
        bulk_cp(qs_b, Qgc, QKV_TILE, mb + 0);
        bulk_cp(sb + 1 * QKV_TILE, Kgc, QKV_TILE, mb + 0);
        bulk_cp(sb + 2 * QKV_TILE, Vgc, QKV_TILE, mb + 0);
        if (qt >= 1) {
            MBAR_EXPECT_TX(mb + 8, 2 * QKV_TILE);
            bulk_cp(sb + 3 * QKV_TILE, Kgc + QKV_TILE, QKV_TILE, mb + 8);
            bulk_cp(sb + 4 * QKV_TILE, Vgc + QKV_TILE, QKV_TILE, mb + 8);
        }
    }

    // fragment lane maps
    const int arow = (lane & 7) + ((lane >> 3) & 1) * 8;
    const int achk = lane >> 4;
    const int brw  = (lane & 7) + ((lane >> 4) & 1) * 8;
    const int bchk = (lane >> 3) & 1;
    const int tq = wid * 16 + arow;     // Q token row
    const int xq = tq & 7;
    const int xk = brw & 7;
    const int xv = arow & 7;
    const uint32_t aoffP = (uint32_t)(tq * ASTR + achk * 16);   // P tile (padded)

    float m0 = -1e30f, m1 = -1e30f, l0 = 0.f, l1 = 0.f;
    float accO[8][4];
    #pragma unroll
    for (int nt = 0; nt < 8; nt++)
        #pragma unroll
        for (int q = 0; q < 4; q++) accO[nt][q] = 0.f;

    const int r0 = lane >> 2;
    const int c0 = (lane & 3) * 2;
    const int row0 = wid * 16 + r0;

    #pragma unroll 1
    for (int kt = 0; kt <= qt; kt++) {
        MBAR_WAIT(mb + (uint32_t)(kt & 1) * 8, (kt >> 1) & 1);
        const uint32_t kbuf = sb + (uint32_t)(1 + 2 * (kt & 1)) * QKV_TILE;
        const uint32_t vbuf = kbuf + QKV_TILE;

        // ---- S = Q @ K^T (3-pass: hi*hi, hi*lo, lo*hi)
        float accS[8][4];
        #pragma unroll
        for (int nt = 0; nt < 8; nt++)
            #pragma unroll
            for (int q = 0; q < 4; q++) accS[nt][q] = 0.f;
        #pragma unroll
        for (int pass = 0; pass < 3; pass++) {
            const int aadd = (pass == 2) ? 8 : 0;
            const int badd = (pass == 1) ? 8 : 0;
            #pragma unroll
            for (int ks = 0; ks < 4; ks++) {
                uint32_t afr[4], bfr[4][4];
                ldm4(afr, qs_b + (uint32_t)(tq * 256 +
                     (((2 * ks + achk + aadd) ^ xq) << 4)));
                #pragma unroll
                for (int n2 = 0; n2 < 4; n2++)
                    ldm4(bfr[n2], kbuf + (uint32_t)((n2 * 16 + brw) * 256 +
                         (((2 * ks + bchk + badd) ^ xk) << 4)));
                #pragma unroll
                for (int nt = 0; nt < 8; nt++)
                    mma16816(accS[nt], afr, &bfr[nt >> 1][(nt & 1) * 2]);
            }
        }

        if (kt == qt) {
            #pragma unroll
            for (int nt = 0; nt < 8; nt++) {
                int col = nt * 8 + c0;
                if (col     > row0)     accS[nt][0] = -1e30f;
                if (col + 1 > row0)     accS[nt][1] = -1e30f;
                if (col     > row0 + 8) accS[nt][2] = -1e30f;
                if (col + 1 > row0 + 8) accS[nt][3] = -1e30f;
            }
        }

        // ---- online softmax + write P (hi/lo into padded Ps)
        {
            float mx0 = -1e30f, mx1 = -1e30f;
            #pragma unroll
            for (int nt = 0; nt < 8; nt++) {
                mx0 = fmaxf(mx0, fmaxf(accS[nt][0], accS[nt][1]));
                mx1 = fmaxf(mx1, fmaxf(accS[nt][2], accS[nt][3]));
            }
            mx0 = fmaxf(mx0, __shfl_xor_sync(0xffffffffu, mx0, 1));
            mx0 = fmaxf(mx0, __shfl_xor_sync(0xffffffffu, mx0, 2));
            mx1 = fmaxf(mx1, __shfl_xor_sync(0xffffffffu, mx1, 1));
            mx1 = fmaxf(mx1, __shfl_xor_sync(0xffffffffu, mx1, 2));

            float mn0 = fmaxf(m0, mx0), mn1 = fmaxf(m1, mx1);
            float al0 = __expf(m0 - mn0), al1 = __expf(m1 - mn1);
            m0 = mn0; m1 = mn1;

            char* prow0 = Psc + (wid * 16 + r0) * ASTR + c0 * 2;
            char* prow1 = prow0 + 8 * ASTR;
            float sum0 = 0.f, sum1 = 0.f;
            #pragma unroll
            for (int nt = 0; nt < 8; nt++) {
                float p0 = __expf(accS[nt][0] - mn0);
                float p1 = __expf(accS[nt][1] - mn0);
                float p2 = __expf(accS[nt][2] - mn1);
                float p3 = __expf(accS[nt][3] - mn1);
                sum0 += p0 + p1; sum1 += p2 + p3;
                __nv_bfloat16 h0 = __float2bfloat16(p0), h1 = __float2bfloat16(p1);
                __nv_bfloat16 h2 = __float2bfloat16(p2), h3 = __float2bfloat16(p3);
                __nv_bfloat16 g0 = __float2bfloat16(p0 - __bfloat162float(h0));
                __nv_bfloat16 g1 = __float2bfloat16(p1 - __bfloat162float(h1));
                __nv_bfloat16 g2 = __float2bfloat16(p2 - __bfloat162float(h2));
                __nv_bfloat16 g3 = __float2bfloat16(p3 - __bfloat162float(h3));
                *(uint32_t*)(prow0 + nt * 16)        = pack_bf2(h0, h1);
                *(uint32_t*)(prow0 + 128 + nt * 16)  = pack_bf2(g0, g1);
                *(uint32_t*)(prow1 + nt * 16)        = pack_bf2(h2, h3);
                *(uint32_t*)(prow1 + 128 + nt * 16)  = pack_bf2(g2, g3);
            }
            sum0 += __shfl_xor_sync(0xffffffffu, sum0, 1);
            sum0 += __shfl_xor_sync(0xffffffffu, sum0, 2);
            sum1 += __shfl_xor_sync(0xffffffffu, sum1, 1);
            sum1 += __shfl_xor_sync(0xffffffffu, sum1, 2);
            l0 = l0 * al0 + sum0;
            l1 = l1 * al1 + sum1;

            #pragma unroll
            for (int nt = 0; nt < 8; nt++) {
                accO[nt][0] *= al0; accO[nt][1] *= al0;
                accO[nt][2] *= al1; accO[nt][3] *= al1;
            }
        }
        __syncwarp();

        // ---- O += P @ V (3-pass; V via ldmatrix.trans, swizzled tile)
        #pragma unroll
        for (int pass = 0; pass < 3; pass++) {
            const uint32_t aadd = (pass == 2) ? 128u : 0u;   // P lo
            const int badd = (pass == 1) ? 8 : 0;            // V lo
            #pragma unroll
            for (int ks = 0; ks < 4; ks++) {
                uint32_t pfr[4], vfr[4][4];
                ldm4(pfr, ps_b + aoffP + aadd + ks * 32);
                #pragma unroll
                for (int n2 = 0; n2 < 4; n2++)
                    ldm4t(vfr[n2], vbuf + (uint32_t)((ks * 16 + arow) * 256 +
                          (((n2 * 2 + achk + badd) ^ xv) << 4)));
                #pragma unroll
                for (int nt = 0; nt < 8; nt++)
                    mma16816(accO[nt], pfr, &vfr[nt >> 1][(nt & 1) * 2]);
            }
        }

        __syncthreads();   // all warps done with this buffer + P
        if (tid == 0 && kt + 2 <= qt) {
            uint32_t mbar = mb + (uint32_t)(kt & 1) * 8;
            uint32_t nb = sb + (uint32_t)(1 + 2 * (kt & 1)) * QKV_TILE;
            MBAR_EXPECT_TX(mbar, 2 * QKV_TILE);
            bulk_cp(nb,            Kgc + ((size_t)(kt + 2) << 14), QKV_TILE, mbar);
            bulk_cp(nb + QKV_TILE, Vgc + ((size_t)(kt + 2) << 14), QKV_TILE, mbar);
        }
    }

    // ---- normalize + write [hi,hi,lo] triplets into TILED-SWIZZLED gA
    float inv0 = 1.f / l0, inv1 = 1.f / l1;
    int grow = qt * 64 + wid * 16 + r0;
    size_t m0r = (size_t)b * T_ + grow;
    size_t m1r = m0r + 8;
    char* Ac = (char*)Aout;
    auto writeWord = [&](size_t m, int o, uint32_t val) {
        int gc = o >> 4, st = gc >> 3, pc = (gc & 7) ^ ((int)m & 7);
        *(uint32_t*)(Ac + (((m >> 7) * NIT + st) << 14)
                        + (m & 127) * 128 + pc * 16 + (o & 15)) = val;
    };
    #pragma unroll
    for (int nt = 0; nt < 8; nt++) {
        int d = nt * 8 + c0;
        int o = (h * D_ + d) * 6;
        float f0 = accO[nt][0] * inv0, f1 = accO[nt][1] * inv0;
        float f2 = accO[nt][2] * inv1, f3 = accO[nt][3] * inv1;
        __nv_bfloat16 h0 = __float2bfloat16(f0);
        __nv_bfloat16 e0 = __float2bfloat16(f0 - __bfloat162float(h0));
        __nv_bfloat16 h1 = __float2bfloat16(f1);
        __nv_bfloat16 e1 = __float2bfloat16(f1 - __bfloat162float(h1));
        __nv_bfloat16 h2 = __float2bfloat16(f2);
        __nv_bfloat16 e2 = __float2bfloat16(f2 - __bfloat162float(h2));
        __nv_bfloat16 h3 = __float2bfloat16(f3);
        __nv_bfloat16 e3 = __float2bfloat16(f3 - __bfloat162float(h3));
        writeWord(m0r, o + 0, pack_bf2(h0, h0));
        writeWord(m0r, o + 4, pack_bf2(e0, h1));
        writeWord(m0r, o + 8, pack_bf2(h1, e1));
        writeWord(m1r, o + 0, pack_bf2(h2, h2));
        writeWord(m1r, o + 4, pack_bf2(e2, h3));
        writeWord(m1r, o + 8, pack_bf2(h3, e3));
    }
}

// ---------------------------------------------------------------------------
extern "C" void kernel_launch(void* const* d_in, const int* in_sizes, int n_in,
                              void* d_out, int out_size)
{
    const float* x     = (const float*)d_in[0];
    const float* Wqkv  = (const float*)d_in[1];
    const float* bqkv  = (const float*)d_in[2];
    const float* Wproj = (const float*)d_in[3];
    const float* bproj = (const float*)d_in[4];
    float* out = (float*)d_out;

    __nv_bfloat16 *gA_p = nullptr, *gBq_p = nullptr, *gBp_p = nullptr;
    __nv_bfloat16 *q_p = nullptr, *k_p = nullptr, *v_p = nullptr;
    cudaGetSymbolAddress((void**)&gA_p,  gA);
    cudaGetSymbolAddress((void**)&gBq_p, gBq);
    cudaGetSymbolAddress((void**)&gBp_p, gBp);
    cudaGetSymbolAddress((void**)&q_p,   gQsp);
    cudaGetSymbolAddress((void**)&k_p,   gKsp);
    cudaGetSymbolAddress((void**)&v_p,   gVsp);

    cudaFuncSetAttribute(attn_mma,
                         cudaFuncAttributeMaxDynamicSharedMemorySize, ATTN_SMEM);
    cudaFuncSetAttribute(gemm_tc<0>,
                         cudaFuncAttributeMaxDynamicSharedMemorySize, GSMEM);
    cudaFuncSetAttribute(gemm_tc<1>,
                         cudaFuncAttributeMaxDynamicSharedMemorySize, GSMEM);

    // conversions (tiled+swizzled outputs)
    convert_w<<<dim3(QKVN / 32, C_ / 32), 128>>>(Wqkv, gBq_p, QKVN);
    convert_w<<<dim3(C_ / 32, C_ / 32), 128>>>(Wproj, gBp_p, C_);
    convert_act<<<(M_ * C_ / 8) / 256, 256>>>(x, gA_p);

    // 1) QKV projection, fused swizzled-tile q/k/v epilogue
    gemm_tc<1><<<dim3(QKVN / 128, M_ / 128), 128, GSMEM>>>(
        gA_p, gBq_p, bqkv, nullptr, QKVN, q_p, k_p, v_p);

    // 2) causal flash attention; epilogue writes proj-input triplets into gA
    attn_mma<<<dim3(T_ / 64, B_ * H_), 128, ATTN_SMEM>>>(q_p, k_p, v_p, gA_p);

    // 3) output projection
    gemm_tc<0><<<dim3(C_ / 128, M_ / 128), 128, GSMEM>>>(
        gA_p, gBp_p, bproj, out, C_, nullptr, nullptr, nullptr);
}